// round 10
// baseline (speedup 1.0000x reference)
#include <cuda_runtime.h>
#include <cstdint>

// Problem constants
#define NB     16
#define NA     1024
#define PP     65536             // pairs per batch
#define NPAIR  (NB * PP)         // 1,048,576
#define NWAVE  8
#define TOT    (NB * NA)         // 16384 atoms
#define CAP    128               // bucket capacity (max count ~99)
#define NU     10                // unique moments: 1, x,y,z, xx,xy,xz,yy,yz,zz
#define CUTOFF 6.0f
#define PI_F   3.14159265358979f

// Scratch (device globals, zero-initialized at module load; k2 self-resets
// cursors so the invariant "cursors==0 on entry" holds for every replay)
__device__ int g_cursor[TOT];
__device__ unsigned int g_packed[NPAIR];                        // (i0<<8)|pos
__device__ __align__(16) float4 g_payload[(size_t)TOT * CAP];   // 32 MB

// ---------------------------------------------------------------------------
// K_pos: atomic-only phase.  Minimal registers, no smem -> near-full
// occupancy so hundreds of atomic returns are in flight per SM.
// Writes (i0<<8)|min(pos,255) coalesced; k_place decodes both.
// 512 blocks x 256 threads x 8 pairs.
// ---------------------------------------------------------------------------
__global__ void __launch_bounds__(256) k_pos(const int* __restrict__ atom_index)
{
    int b     = blockIdx.x >> 5;                     // 32 blocks per batch
    int pbase = (blockIdx.x & 31) * 2048 + threadIdx.x;
    const int* ai0 = atom_index + (size_t)b * 2 * PP;

    int i0[8];
#pragma unroll
    for (int k = 0; k < 8; k++) i0[k] = ai0[pbase + k * 256];

    int pos[8];
#pragma unroll
    for (int k = 0; k < 8; k++)
        pos[k] = atomicAdd(&g_cursor[b * NA + i0[k]], 1);

#pragma unroll
    for (int k = 0; k < 8; k++) {
        unsigned int p = (unsigned int)(i0[k] << 8) |
                         (unsigned int)(pos[k] < 255 ? pos[k] : 255);
        g_packed[(size_t)b * PP + pbase + k * 256] = p;
    }
}

// ---------------------------------------------------------------------------
// K_place: no atomics.  Reads packed slots (coalesced), neighbor indices +
// shifts (coalesced), gathers coords from smem, scattered STG.128 of the
// payload (ux, uy, uz, dist).  512 blocks x 256 threads x 8 pairs.
// ---------------------------------------------------------------------------
__global__ void __launch_bounds__(256, 4) k_place(
    const int*   __restrict__ atom_index,
    const float* __restrict__ shifts,
    const float* __restrict__ coords)
{
    __shared__ float sc[NA * 3];   // 12 KB: this batch's coordinates
    int b     = blockIdx.x >> 5;
    int pbase = (blockIdx.x & 31) * 2048 + threadIdx.x;

    const int* ai1 = atom_index + (size_t)b * 2 * PP + PP;

    // stage this batch's coords in smem (overlaps the loads below)
    const float* cb = coords + (size_t)b * NA * 3;
    for (int i = threadIdx.x; i < NA * 3; i += 256) sc[i] = cb[i];

    unsigned int pk[8];
    int i1[8];
#pragma unroll
    for (int k = 0; k < 8; k++) {
        pk[k] = g_packed[(size_t)b * PP + pbase + k * 256];
        i1[k] = ai1[pbase + k * 256];
    }
    __syncthreads();

    const float* shb = shifts + (size_t)b * PP * 3;
#pragma unroll
    for (int k = 0; k < 8; k++) {
        int p   = pbase + k * 256;
        int i0  = (int)(pk[k] >> 8);
        int pos = (int)(pk[k] & 0xFF);

        float sx = shb[(size_t)p * 3 + 0];
        float sy = shb[(size_t)p * 3 + 1];
        float sz = shb[(size_t)p * 3 + 2];

        float dx = sc[i0 * 3 + 0] - sc[i1[k] * 3 + 0] + sx;
        float dy = sc[i0 * 3 + 1] - sc[i1[k] * 3 + 1] + sy;
        float dz = sc[i0 * 3 + 2] - sc[i1[k] * 3 + 2] + sz;
        // Invalid shifts (<= -1e9) give huge dist -> fcut=0 and radial exp
        // underflow downstream, matching the reference's where(valid,...,0).
        float dist = sqrtf(dx * dx + dy * dy + dz * dz);
        float inv  = (dist > 1e-12f) ? (1.f / dist) : 1.f;
        if (pos < CAP) {
            g_payload[(size_t)(b * NA + i0) * CAP + pos] =
                make_float4(dx * inv, dy * inv, dz * inv, dist);
        }
    }
}

// ---------------------------------------------------------------------------
// K2: per-atom gather + finalize.  8 threads per atom: 4 w-threads x 2 list
// halves (h).  10 unique symmetric moments per wave; fcut folded into the
// radials; duplicates folded into the final sum as 2*(xy^2+xz^2+yz^2).
// Single shfl_xor(4) combine.  Self-resets g_cursor for the next replay.
// ---------------------------------------------------------------------------
__device__ __forceinline__ void body(
    float4 v, float rs0, float rs1, float ia0, float ia1,
    float* u0, float* u1)
{
    float ux = v.x, uy = v.y, uz = v.z, dist = v.w;
    float xc   = fminf(dist * (1.f / CUTOFF), 1.f);
    float fcut = 0.5f * (__cosf(PI_F * xc) + 1.f);

    float t0 = dist - rs0, t1 = dist - rs1;
    float fr0 = fcut * __expf(-ia0 * t0 * t0);
    float fr1 = fcut * __expf(-ia1 * t1 * t1);

    float m[NU];
    m[0] = 1.f;
    m[1] = ux;      m[2] = uy;      m[3] = uz;
    m[4] = ux * ux; m[5] = ux * uy; m[6] = ux * uz;
    m[7] = uy * uy; m[8] = uy * uz; m[9] = uz * uz;

#pragma unroll
    for (int k = 0; k < NU; k++) {
        u0[k] = fmaf(m[k], fr0, u0[k]);
        u1[k] = fmaf(m[k], fr1, u1[k]);
    }
}

__global__ void __launch_bounds__(256, 4) k2_compute(
    const int*   __restrict__ species,
    const float* __restrict__ rs,
    const float* __restrict__ inta,
    const float* __restrict__ params,
    float*       __restrict__ out)
{
    int tid = blockIdx.x * 256 + threadIdx.x;   // TOT*8 threads
    int n   = tid >> 3;                         // atom
    int w0  = (tid & 3) * 2;                    // wave pair
    int h   = (tid >> 2) & 1;                   // list half

    int spec = species[n];
    float rs0 = rs[spec * NWAVE + w0],   rs1 = rs[spec * NWAVE + w0 + 1];
    float ia0 = inta[spec * NWAVE + w0], ia1 = inta[spec * NWAVE + w0 + 1];

    int cnt = g_cursor[n];
    if (cnt > CAP) cnt = CAP;
    // self-reset for next graph replay (warp-synchronous: all 8 lanes of
    // this atom read cnt above before any lane stores — same instr stream)
    if ((tid & 7) == 0) g_cursor[n] = 0;

    float u0[NU], u1[NU];
#pragma unroll
    for (int k = 0; k < NU; k++) { u0[k] = 0.f; u1[k] = 0.f; }

    const float4* pl = g_payload + (size_t)n * CAP;
    float4 dummy = make_float4(0.f, 0.f, 0.f, 1e9f);

    // strided loop j = h, h+2, ... with prefetch depth 2
    float4 v0 = (h     < cnt) ? pl[h]     : dummy;
    float4 v1 = (h + 2 < cnt) ? pl[h + 2] : dummy;

    int j = h;
    for (; j + 2 < cnt; j += 4) {
        float4 n0 = (j + 4 < cnt) ? pl[j + 4] : dummy;
        float4 n1 = (j + 6 < cnt) ? pl[j + 6] : dummy;
        body(v0, rs0, rs1, ia0, ia1, u0, u1);
        body(v1, rs0, rs1, ia0, ia1, u0, u1);
        v0 = n0; v1 = n1;
    }
    if (j < cnt) body(v0, rs0, rs1, ia0, ia1, u0, u1);

    // combine the 2 list-halves (partner lane differs in bit 2)
#pragma unroll
    for (int k = 0; k < NU; k++) {
        u0[k] += __shfl_xor_sync(0xFFFFFFFF, u0[k], 4);
        u1[k] += __shfl_xor_sync(0xFFFFFFFF, u1[k], 4);
    }

    if (h == 0) {
        float pm = params[spec];
        float s00 = u0[0] * u0[0];
        float s01 = u1[0] * u1[0];
        float s10 = u0[1]*u0[1] + u0[2]*u0[2] + u0[3]*u0[3];
        float s11 = u1[1]*u1[1] + u1[2]*u1[2] + u1[3]*u1[3];
        // diag + 2x off-diag (xy,xz,yz appear twice in the reference's 9)
        float s20 = u0[4]*u0[4] + u0[7]*u0[7] + u0[9]*u0[9]
                  + 2.f * (u0[5]*u0[5] + u0[6]*u0[6] + u0[8]*u0[8]);
        float s21 = u1[4]*u1[4] + u1[7]*u1[7] + u1[9]*u1[9]
                  + 2.f * (u1[5]*u1[5] + u1[6]*u1[6] + u1[8]*u1[8]);

        float* o = out + (size_t)n * 24;
        o[0  + w0] = pm * s00;  o[0  + w0 + 1] = pm * s01;
        o[8  + w0] = pm * s10;  o[8  + w0 + 1] = pm * s11;
        o[16 + w0] = pm * s20;  o[16 + w0 + 1] = pm * s21;
    }
}

// ---------------------------------------------------------------------------
// Launch
// ---------------------------------------------------------------------------
extern "C" void kernel_launch(void* const* d_in, const int* in_sizes, int n_in,
                              void* d_out, int out_size) {
    const float* coords     = (const float*)d_in[0];
    // d_in[1] = numatoms (unused)
    const int*   atom_index = (const int*)  d_in[2];
    const float* shifts     = (const float*)d_in[3];
    const int*   species    = (const int*)  d_in[4];
    const float* rs         = (const float*)d_in[5];
    const float* inta       = (const float*)d_in[6];
    const float* params     = (const float*)d_in[7];
    float* out = (float*)d_out;

    k_pos  <<<512, 256>>>(atom_index);
    k_place<<<512, 256>>>(atom_index, shifts, coords);
    k2_compute<<<TOT * 8 / 256, 256>>>(species, rs, inta, params, out);
}